// round 17
// baseline (speedup 1.0000x reference)
#include <cuda_runtime.h>
#include <math_constants.h>
#include <cstdint>

// Problem constants (fixed by the reference)
#define BB 2
#define TT 512
#define EE 1024
#define SS 2048
#define AA 30

#define NB2 (TT * 4)            // sort key: t0*4 + (w-1)/8
#define NPAIRS_MAX 1280         // sum ceil(n_t/2) <= (2048 + 512)/2
#define CHUNK 4                 // rows per cp.async chunk

__device__ float g_scores[BB * TT];
__device__ int   g_sorted[SS];
// pair descriptor: x = s0 | s1<<11 | (w0-1)<<22 | (w1-1)<<27 ; y = t0 | cnt<<10
__device__ int2  g_pairs[NPAIRS_MAX];
__device__ int   g_npairs;

#define CP_ASYNC16(smem_u32, gptr) \
    asm volatile("cp.async.cg.shared.global [%0], [%1], 16;" \
                 :: "r"(smem_u32), "l"(gptr) : "memory")
#define CP_COMMIT() asm volatile("cp.async.commit_group;" ::: "memory")
#define CP_WAIT(N)  asm volatile("cp.async.wait_group %0;" :: "n"(N) : "memory")

// ---------------------------------------------------------------------------
// Prep kernel (fused): blocks 0..31 compute scores (warp-per-row); block 32
// runs the counting sort by (t0, w-tier) and emits packed span PAIRS.
// ---------------------------------------------------------------------------
__global__ __launch_bounds__(1024)
void prep_kernel(const float* __restrict__ x,
                 const float* __restrict__ W,
                 const float* __restrict__ bias,
                 const int* __restrict__ start,
                 const int* __restrict__ end) {
    __shared__ int bins[NB2];            // 8 KB (sort block only)
    __shared__ int t0_off[TT + 1];
    __shared__ int aux[32];
    __shared__ int aux2[32];

    const int tid  = threadIdx.x;
    const int lane = tid & 31;
    const int wrp  = tid >> 5;

    if (blockIdx.x < 32) {
        // ---------------- score part: 32 blocks x 32 warps = 1024 rows ------
        const int row = blockIdx.x * 32 + wrp;
        const float4* __restrict__ xr =
            reinterpret_cast<const float4*>(x) + (size_t)row * 256;
        const float4* __restrict__ w4 = reinterpret_cast<const float4*>(W);

        float acc = 0.0f;
#pragma unroll
        for (int i = 0; i < 8; ++i) {
            const float4 xv = xr[lane + i * 32];
            const float4 wv = w4[lane + i * 32];
            acc += xv.x * wv.x + xv.y * wv.y + xv.z * wv.z + xv.w * wv.w;
        }
#pragma unroll
        for (int off = 16; off; off >>= 1)
            acc += __shfl_xor_sync(0xffffffffu, acc, off);

        if (lane == 0)
            g_scores[row] = fmaxf(acc + bias[0], 0.0f);
        return;
    }

    // ---------------- sort part: single block (blockIdx.x == 32) -----------
    for (int i = tid; i < NB2; i += 1024) bins[i] = 0;
    __syncthreads();

    for (int s = tid; s < SS; s += 1024) {
        const int t0 = start[s];
        const int w  = end[s] - t0 + 1;
        atomicAdd(&bins[t0 * 4 + ((w - 1) >> 3)], 1);
    }
    __syncthreads();

    // exclusive scan over 2048 bins (2 per thread + block scan)
    const int v0 = bins[2 * tid], v1 = bins[2 * tid + 1];
    const int run = v0 + v1;
    int inc = run;
#pragma unroll
    for (int off = 1; off < 32; off <<= 1) {
        const int t = __shfl_up_sync(0xffffffffu, inc, off);
        if (lane >= off) inc += t;
    }
    if (lane == 31) aux[wrp] = inc;
    __syncthreads();
    if (wrp == 0) {
        int a = aux[lane];
#pragma unroll
        for (int off = 1; off < 32; off <<= 1) {
            const int t = __shfl_up_sync(0xffffffffu, a, off);
            if (lane >= off) a += t;
        }
        aux[lane] = a;
    }
    __syncthreads();
    const int ex = inc - run + (wrp ? aux[wrp - 1] : 0);
    bins[2 * tid]     = ex;
    bins[2 * tid + 1] = ex + v0;
    __syncthreads();

    if (tid < TT) t0_off[tid] = bins[tid * 4];
    if (tid == 0) t0_off[TT] = SS;
    __syncthreads();

    for (int s = tid; s < SS; s += 1024) {
        const int t0 = start[s];
        const int w  = end[s] - t0 + 1;
        const int pos = atomicAdd(&bins[t0 * 4 + ((w - 1) >> 3)], 1);
        g_sorted[pos] = s;
    }
    __syncthreads();

    // scan per-t0 PAIR counts (all 1024 threads; 0 past TT)
    int gc = 0;
    if (tid < TT) gc = (t0_off[tid + 1] - t0_off[tid] + 1) >> 1;
    int gi = gc;
#pragma unroll
    for (int off = 1; off < 32; off <<= 1) {
        const int t = __shfl_up_sync(0xffffffffu, gi, off);
        if (lane >= off) gi += t;
    }
    if (lane == 31) aux2[wrp] = gi;
    __syncthreads();
    if (wrp == 0) {
        int a = aux2[lane];
#pragma unroll
        for (int off = 1; off < 32; off <<= 1) {
            const int t = __shfl_up_sync(0xffffffffu, a, off);
            if (lane >= off) a += t;
        }
        aux2[lane] = a;
    }
    __syncthreads();
    const int incl = gi + (wrp ? aux2[wrp - 1] : 0);
    const int g0   = incl - gc;

    if (tid < TT) {
        const int b0 = t0_off[tid];
        const int n  = t0_off[tid + 1] - b0;
        for (int k = 0, q = 0; k < n; k += 2, ++q) {
            const int cnt = min(2, n - k);
            const int s0 = g_sorted[b0 + k];
            const int s1 = g_sorted[b0 + k + cnt - 1];     // dup for cnt==1
            const int w0 = end[s0] - tid + 1;              // 1..30
            const int w1 = end[s1] - tid + 1;
            g_pairs[g0 + q] = make_int2(
                s0 | (s1 << 11) | ((w0 - 1) << 22) | ((w1 - 1) << 27),
                tid | (cnt << 10));
        }
    }
    if (tid == 1023) g_npairs = incl;
}

// ---------------------------------------------------------------------------
// Main kernel: block per (pair, batch). 256 threads cover E = 1024 floats.
// cp.async double-buffered pipeline: gmem rows stream into a 2 x 4-row smem
// ring with ZERO register cost; compute consumes from smem (29-cyc LDS).
// Startup: one broadcast LDG.64 of the fully-packed descriptor; warps 0/1
// compute the two softmaxes inline while prefetch chunks 0/1 are in flight.
// Zero probs past each width make clamped/padded rows contribute exactly 0.
// ---------------------------------------------------------------------------
__global__ __launch_bounds__(256)
void main_kernel(const float* __restrict__ x,
                 float* __restrict__ out) {
    const int gidx = blockIdx.x;
    if (gidx >= g_npairs) return;
    const int b = blockIdx.y;

    __shared__ __align__(16) float rows[2][CHUNK * EE];   // 32 KB ring
    __shared__ __align__(8)  float p2f[64];

    const int tid  = threadIdx.x;
    const int lane = tid & 31;
    const int wrp  = tid >> 5;

    const int2 pd = __ldg(&g_pairs[gidx]);
    const int s0   = pd.x & 0x7ff;
    const int s1   = (pd.x >> 11) & 0x7ff;
    const int w0   = ((pd.x >> 22) & 0x1f) + 1;
    const int w1   = ((pd.x >> 27) & 0x1f) + 1;
    const int t0   = pd.y & 0x1ff;
    const int cnt  = (pd.y >> 10) & 3;

    const int wmax = max(w0, w1);
    const int wm1  = wmax - 1;
    const int nch  = (wmax + CHUNK - 1) >> 2;

    const float* __restrict__ xrow = x + ((size_t)b * TT + t0) * EE;

    // ---- prefetch chunks 0 and (if any) 1 ----
    const uint32_t smem_base =
        (uint32_t)__cvta_generic_to_shared(&rows[0][0]);
#define PREFETCH(c)                                                         \
    do {                                                                    \
        const uint32_t sb = smem_base + ((c) & 1) * (CHUNK * EE * 4);       \
        _Pragma("unroll")                                                   \
        for (int k = 0; k < CHUNK; ++k) {                                   \
            const int r = min((c) * CHUNK + k, wm1);                        \
            CP_ASYNC16(sb + (uint32_t)(k * EE + tid * 4) * 4,               \
                       xrow + (size_t)r * EE + tid * 4);                    \
        }                                                                   \
        CP_COMMIT();                                                        \
    } while (0)

    PREFETCH(0);
    if (nch > 1) PREFETCH(1);

    // ---- inline softmax: warp 0 -> member 0, warp 1 -> member 1 ----
    if (wrp < 2) {
        const int w = wrp ? w1 : w0;
        float sc = (lane < w) ? g_scores[b * TT + t0 + lane] : -CUDART_INF_F;
        float m = sc;
#pragma unroll
        for (int off = 16; off; off >>= 1)
            m = fmaxf(m, __shfl_xor_sync(0xffffffffu, m, off));
        const float e = (lane < w) ? __expf(sc - m) : 0.0f;
        float sum = e;
#pragma unroll
        for (int off = 16; off; off >>= 1)
            sum += __shfl_xor_sync(0xffffffffu, sum, off);
        p2f[lane * 2 + wrp] = e / sum;        // exactly 0 past w
    }

    const float2* __restrict__ p2 = reinterpret_cast<const float2*>(p2f);

    float4 a0 = make_float4(0.f, 0.f, 0.f, 0.f);
    float4 a1 = make_float4(0.f, 0.f, 0.f, 0.f);

#pragma unroll 1
    for (int c = 0; c < nch; ++c) {
        if (c < nch - 1) { CP_WAIT(1); } else { CP_WAIT(0); }
        __syncthreads();                       // chunk c (and p2f) visible

        const float* rbuf = &rows[c & 1][0];
#pragma unroll
        for (int k = 0; k < CHUNK; ++k) {
            const int j = c * CHUNK + k;       // <= 31
            const float2 q = p2[j];
            const float4 v =
                *reinterpret_cast<const float4*>(rbuf + k * EE + tid * 4);
            a0.x += q.x * v.x; a0.y += q.x * v.y;
            a0.z += q.x * v.z; a0.w += q.x * v.w;
            a1.x += q.y * v.x; a1.y += q.y * v.y;
            a1.z += q.y * v.z; a1.w += q.y * v.w;
        }

        if (c + 2 < nch) {
            __syncthreads();                   // all done reading buf (c&1)
            PREFETCH(c + 2);
        }
    }

    float4* __restrict__ o4 =
        reinterpret_cast<float4*>(out) + (size_t)b * SS * 256 + tid;
    o4[(size_t)s0 * 256] = a0;
    if (cnt > 1) o4[(size_t)s1 * 256] = a1;
#undef PREFETCH
}

// ---------------------------------------------------------------------------
// Launch
// Inputs (metadata order): x (B,T,E) f32, W (E,1) f32, b (1,) f32,
//                          start (S,) i32, end (S,) i32
// Output: (B, S, E) f32
// ---------------------------------------------------------------------------
extern "C" void kernel_launch(void* const* d_in, const int* in_sizes, int n_in,
                              void* d_out, int out_size) {
    const float* x     = (const float*)d_in[0];
    const float* W     = (const float*)d_in[1];
    const float* bias  = (const float*)d_in[2];
    const int*   start = (const int*)d_in[3];
    const int*   end   = (const int*)d_in[4];
    float*       out   = (float*)d_out;

    // Fused prep: blocks 0..31 = scores, block 32 = sort + pair building
    prep_kernel<<<33, 1024>>>(x, W, bias, start, end);

    // Main: block per (pair, batch), cp.async pipelined
    dim3 grid(NPAIRS_MAX, BB);
    main_kernel<<<grid, 256>>>(x, out);
}